// round 1
// baseline (speedup 1.0000x reference)
#include <cuda_runtime.h>
#include <math.h>

#define BSZ 4
#define SEQ 2048
#define DMODEL 1024
#define NHEADS 8
#define DH 128
#define NEG_INF -1e9f

#define BM 128
#define BN 128
#define BK 16

// ---------------- static device scratch (no allocations allowed) ----------------
__device__ float g_Q[BSZ * NHEADS * SEQ * DH];     // [b,h,n,e]
__device__ float g_K[BSZ * NHEADS * SEQ * DH];
__device__ float g_V[BSZ * NHEADS * SEQ * DH];
__device__ float g_AP[SEQ * SEQ];
__device__ float g_A[(size_t)BSZ * NHEADS * SEQ * SEQ];  // per (b,h): 2048x2048
__device__ float g_Y[BSZ * SEQ * DMODEL];          // [b,n,D]

// ---------------- AP precompute ----------------
__global__ void ap_kernel(float* __restrict__ AP) {
    int idx = blockIdx.x * blockDim.x + threadIdx.x;
    const int total = SEQ * (SEQ / 2);
    if (idx >= total) return;
    int p = idx / (SEQ / 2);
    int i = idx % (SEQ / 2);
    // angle = p / freq^(2i/d), d = 1024, freq = 10000 (match reference fp32 math)
    float denom = powf(10000.0f, (2.0f * (float)i) / 1024.0f);
    float angle = (float)p / denom;
    float s, c;
    sincosf(angle, &s, &c);
    AP[(size_t)p * SEQ + 2 * i]     = s;
    AP[(size_t)p * SEQ + 2 * i + 1] = c;
}

// ---------------- shared GEMM mainloop: C(128x128) += A(MxK) * B(NxK)^T ----------------
// A row-major [*, lda], B row-major [*, ldb], K multiple of 16, lda/ldb multiple of 4.
__device__ __forceinline__ void gemm_nt_core(
    const float* __restrict__ Ag,   // tile base: A + tileM*lda
    const float* __restrict__ Bg,   // tile base: B + tileN*ldb
    int K, int lda, int ldb,
    float (&As)[BK][BM + 4], float (&Bs)[BK][BN + 4],
    float acc[8][8])
{
    const int tid = threadIdx.x;        // 256 threads
    const int lr  = tid >> 2;           // 0..63
    const int lc  = (tid & 3) << 2;     // 0,4,8,12
    const int tx  = tid & 15;
    const int ty  = tid >> 4;

    for (int k0 = 0; k0 < K; k0 += BK) {
        float4 a0 = *(const float4*)(Ag + (size_t)lr        * lda + k0 + lc);
        float4 a1 = *(const float4*)(Ag + (size_t)(lr + 64) * lda + k0 + lc);
        float4 b0 = *(const float4*)(Bg + (size_t)lr        * ldb + k0 + lc);
        float4 b1 = *(const float4*)(Bg + (size_t)(lr + 64) * ldb + k0 + lc);
        __syncthreads();
        As[lc + 0][lr] = a0.x; As[lc + 1][lr] = a0.y; As[lc + 2][lr] = a0.z; As[lc + 3][lr] = a0.w;
        As[lc + 0][lr + 64] = a1.x; As[lc + 1][lr + 64] = a1.y; As[lc + 2][lr + 64] = a1.z; As[lc + 3][lr + 64] = a1.w;
        Bs[lc + 0][lr] = b0.x; Bs[lc + 1][lr] = b0.y; Bs[lc + 2][lr] = b0.z; Bs[lc + 3][lr] = b0.w;
        Bs[lc + 0][lr + 64] = b1.x; Bs[lc + 1][lr + 64] = b1.y; Bs[lc + 2][lr + 64] = b1.z; Bs[lc + 3][lr + 64] = b1.w;
        __syncthreads();
        #pragma unroll
        for (int kk = 0; kk < BK; kk++) {
            float4 av0 = *(const float4*)&As[kk][ty * 8];
            float4 av1 = *(const float4*)&As[kk][ty * 8 + 4];
            float4 bv0 = *(const float4*)&Bs[kk][tx * 8];
            float4 bv1 = *(const float4*)&Bs[kk][tx * 8 + 4];
            float a[8] = {av0.x, av0.y, av0.z, av0.w, av1.x, av1.y, av1.z, av1.w};
            float b[8] = {bv0.x, bv0.y, bv0.z, bv0.w, bv1.x, bv1.y, bv1.z, bv1.w};
            #pragma unroll
            for (int i = 0; i < 8; i++)
                #pragma unroll
                for (int j = 0; j < 8; j++)
                    acc[i][j] = fmaf(a[i], b[j], acc[i][j]);
        }
    }
}

// ---------------- projection: out[b,h,n,e] = x[m,:] . W[n,:] ----------------
__global__ void __launch_bounds__(256) proj_kernel(
    const float* __restrict__ x, const float* __restrict__ W, float* __restrict__ outp)
{
    __shared__ float As[BK][BM + 4];
    __shared__ float Bs[BK][BN + 4];
    float acc[8][8] = {};
    const int tileM = blockIdx.y * BM;   // over 8192 = b*2048+n
    const int tileN = blockIdx.x * BN;   // over 1024 = h*128+e
    gemm_nt_core(x + (size_t)tileM * DMODEL, W + (size_t)tileN * DMODEL,
                 DMODEL, DMODEL, DMODEL, As, Bs, acc);

    const int tx = threadIdx.x & 15, ty = threadIdx.x >> 4;
    const int n0 = tileN + tx * 8;
    const int h  = n0 >> 7;
    const int e0 = n0 & 127;
    #pragma unroll
    for (int i = 0; i < 8; i++) {
        int m = tileM + ty * 8 + i;
        int b = m >> 11, nseq = m & 2047;
        float* dst = outp + (((size_t)(b * NHEADS + h) * SEQ + nseq) * DH + e0);
        *(float4*)(dst + 0) = make_float4(acc[i][0], acc[i][1], acc[i][2], acc[i][3]);
        *(float4*)(dst + 4) = make_float4(acc[i][4], acc[i][5], acc[i][6], acc[i][7]);
    }
}

// ---------------- scores: S = Q K^T + AP, masked; per (b,h) ----------------
__global__ void __launch_bounds__(256) scores_kernel(
    const float* __restrict__ Q, const float* __restrict__ Km,
    const int* __restrict__ mask, const float* __restrict__ AP,
    float* __restrict__ Ascr, float* __restrict__ attOut, int hasAtt)
{
    __shared__ float As[BK][BM + 4];
    __shared__ float Bs[BK][BN + 4];
    float acc[8][8] = {};
    const int bh = blockIdx.z;
    const int b = bh >> 3, h = bh & 7;
    const float* Ag = Q  + (size_t)bh * SEQ * DH + (size_t)blockIdx.y * BM * DH;
    const float* Bg = Km + (size_t)bh * SEQ * DH + (size_t)blockIdx.x * BN * DH;
    gemm_nt_core(Ag, Bg, DH, DH, DH, As, Bs, acc);

    float* C = (h == 7 && hasAtt) ? attOut + (size_t)b * SEQ * SEQ
                                  : Ascr   + (size_t)bh * SEQ * SEQ;
    const int tx = threadIdx.x & 15, ty = threadIdx.x >> 4;
    const int r0 = blockIdx.y * BM + ty * 8;
    const int c0 = blockIdx.x * BN + tx * 8;
    const int* mb = mask + b * SEQ;
    int mc[8];
    #pragma unroll
    for (int j = 0; j < 8; j++) mc[j] = mb[c0 + j];
    #pragma unroll
    for (int i = 0; i < 8; i++) {
        int r = r0 + i;
        int mr = mb[r];
        const float* ap = AP + (size_t)r * SEQ + c0;
        float* dst = C + (size_t)r * SEQ + c0;
        float v[8];
        #pragma unroll
        for (int j = 0; j < 8; j++) {
            float s = acc[i][j] + ap[j];
            v[j] = (mr && mc[j]) ? s : NEG_INF;
        }
        *(float4*)(dst + 0) = make_float4(v[0], v[1], v[2], v[3]);
        *(float4*)(dst + 4) = make_float4(v[4], v[5], v[6], v[7]);
    }
}

// ---------------- row softmax (one block per row) ----------------
__global__ void __launch_bounds__(256) softmax_kernel(
    float* __restrict__ Ascr, float* __restrict__ attOut, int hasAtt)
{
    const int row = blockIdx.x;          // 0..BSZ*NHEADS*SEQ-1
    const int bh = row >> 11;
    const int q  = row & 2047;
    const int b = bh >> 3, h = bh & 7;
    float* base = (h == 7 && hasAtt) ? attOut + (size_t)b * SEQ * SEQ
                                     : Ascr   + (size_t)bh * SEQ * SEQ;
    float* rp = base + (size_t)q * SEQ;

    const int t = threadIdx.x;           // 256
    float v[8];
    #pragma unroll
    for (int i = 0; i < 8; i++) v[i] = rp[t + i * 256];

    float m = v[0];
    #pragma unroll
    for (int i = 1; i < 8; i++) m = fmaxf(m, v[i]);

    __shared__ float sdata[256];
    sdata[t] = m;
    __syncthreads();
    for (int s = 128; s > 0; s >>= 1) {
        if (t < s) sdata[t] = fmaxf(sdata[t], sdata[t + s]);
        __syncthreads();
    }
    const float mx = sdata[0];
    __syncthreads();

    float sum = 0.f;
    #pragma unroll
    for (int i = 0; i < 8; i++) { v[i] = expf(v[i] - mx); sum += v[i]; }
    sdata[t] = sum;
    __syncthreads();
    for (int s = 128; s > 0; s >>= 1) {
        if (t < s) sdata[t] += sdata[t + s];
        __syncthreads();
    }
    const float inv = 1.0f / sdata[0];
    #pragma unroll
    for (int i = 0; i < 8; i++) rp[t + i * 256] = v[i] * inv;
}

// ---------------- y = A^T V per (b,h): C[2048,128] = A^T[2048x2048] * V[2048x128] ----------------
__global__ void __launch_bounds__(256) av_kernel(
    const float* __restrict__ V, const float* __restrict__ Ascr,
    const float* __restrict__ attOut, int hasAtt, float* __restrict__ Y)
{
    __shared__ float As[BK][BM + 4];
    __shared__ float Bs[BK][BN + 4];
    float acc[8][8] = {};
    const int bh = blockIdx.y;
    const int b = bh >> 3, h = bh & 7;
    const float* Abase = (h == 7 && hasAtt) ? attOut + (size_t)b * SEQ * SEQ
                                            : Ascr   + (size_t)bh * SEQ * SEQ;
    const float* Vb = V + (size_t)bh * SEQ * DH;
    const int tileM = blockIdx.x * BM;   // i (output seq) tile

    const int tid = threadIdx.x;
    const int kr = tid >> 4;             // 0..15
    const int cc = (tid & 15) * 8;       // 0..120 step 8
    const int tx = tid & 15, ty = tid >> 4;

    for (int k0 = 0; k0 < SEQ; k0 += BK) {
        float4 a0 = *(const float4*)(Abase + (size_t)(k0 + kr) * SEQ + tileM + cc);
        float4 a1 = *(const float4*)(Abase + (size_t)(k0 + kr) * SEQ + tileM + cc + 4);
        float4 b0 = *(const float4*)(Vb + (size_t)(k0 + kr) * DH + cc);
        float4 b1 = *(const float4*)(Vb + (size_t)(k0 + kr) * DH + cc + 4);
        __syncthreads();
        *(float4*)&As[kr][cc]     = a0;
        *(float4*)&As[kr][cc + 4] = a1;
        *(float4*)&Bs[kr][cc]     = b0;
        *(float4*)&Bs[kr][cc + 4] = b1;
        __syncthreads();
        #pragma unroll
        for (int kk = 0; kk < BK; kk++) {
            float4 av0 = *(const float4*)&As[kk][ty * 8];
            float4 av1 = *(const float4*)&As[kk][ty * 8 + 4];
            float4 bv0 = *(const float4*)&Bs[kk][tx * 8];
            float4 bv1 = *(const float4*)&Bs[kk][tx * 8 + 4];
            float a[8] = {av0.x, av0.y, av0.z, av0.w, av1.x, av1.y, av1.z, av1.w};
            float bb[8] = {bv0.x, bv0.y, bv0.z, bv0.w, bv1.x, bv1.y, bv1.z, bv1.w};
            #pragma unroll
            for (int i = 0; i < 8; i++)
                #pragma unroll
                for (int j = 0; j < 8; j++)
                    acc[i][j] = fmaf(a[i], bb[j], acc[i][j]);
        }
    }

    #pragma unroll
    for (int i = 0; i < 8; i++) {
        int iseq = tileM + ty * 8 + i;
        float* dst = Y + ((size_t)b * SEQ + iseq) * DMODEL + h * DH + tx * 8;
        *(float4*)(dst + 0) = make_float4(acc[i][0], acc[i][1], acc[i][2], acc[i][3]);
        *(float4*)(dst + 4) = make_float4(acc[i][4], acc[i][5], acc[i][6], acc[i][7]);
    }
}

// ---------------- out = Y * Wout^T ----------------
__global__ void __launch_bounds__(256) outproj_kernel(
    const float* __restrict__ Y, const float* __restrict__ Wout, float* __restrict__ out)
{
    __shared__ float As[BK][BM + 4];
    __shared__ float Bs[BK][BN + 4];
    float acc[8][8] = {};
    const int tileM = blockIdx.y * BM;
    const int tileN = blockIdx.x * BN;
    gemm_nt_core(Y + (size_t)tileM * DMODEL, Wout + (size_t)tileN * DMODEL,
                 DMODEL, DMODEL, DMODEL, As, Bs, acc);

    const int tx = threadIdx.x & 15, ty = threadIdx.x >> 4;
    #pragma unroll
    for (int i = 0; i < 8; i++) {
        int m = tileM + ty * 8 + i;
        float* dst = out + (size_t)m * DMODEL + tileN + tx * 8;
        *(float4*)(dst + 0) = make_float4(acc[i][0], acc[i][1], acc[i][2], acc[i][3]);
        *(float4*)(dst + 4) = make_float4(acc[i][4], acc[i][5], acc[i][6], acc[i][7]);
    }
}

// ---------------- launch ----------------
extern "C" void kernel_launch(void* const* d_in, const int* in_sizes, int n_in,
                              void* d_out, int out_size) {
    const float* x    = (const float*)d_in[0];
    const int*   mask = (const int*)  d_in[1];
    const float* Wq   = (const float*)d_in[2];
    const float* Wk   = (const float*)d_in[3];
    const float* Wv   = (const float*)d_in[4];
    const float* Wout = (const float*)d_in[5];
    float* out = (float*)d_out;

    const long long outElems = (long long)BSZ * SEQ * DMODEL;          // 8388608
    const long long attElems = (long long)BSZ * SEQ * SEQ;             // 16777216
    int hasAtt = ((long long)out_size >= outElems + attElems) ? 1 : 0;
    float* attOut = out + outElems;

    float *Qp, *Kp, *Vp, *APp, *Ap, *Yp;
    cudaGetSymbolAddress((void**)&Qp,  g_Q);
    cudaGetSymbolAddress((void**)&Kp,  g_K);
    cudaGetSymbolAddress((void**)&Vp,  g_V);
    cudaGetSymbolAddress((void**)&APp, g_AP);
    cudaGetSymbolAddress((void**)&Ap,  g_A);
    cudaGetSymbolAddress((void**)&Yp,  g_Y);

    // 1. AP table
    {
        int total = SEQ * (SEQ / 2);
        ap_kernel<<<(total + 255) / 256, 256>>>(APp);
    }
    // 2. projections
    {
        dim3 g(DMODEL / BN, (BSZ * SEQ) / BM);
        proj_kernel<<<g, 256>>>(x, Wq, Qp);
        proj_kernel<<<g, 256>>>(x, Wk, Kp);
        proj_kernel<<<g, 256>>>(x, Wv, Vp);
    }
    // 3. scores + AP + mask
    {
        dim3 g(SEQ / BN, SEQ / BM, BSZ * NHEADS);
        scores_kernel<<<g, 256>>>(Qp, Kp, mask, APp, Ap, attOut, hasAtt);
    }
    // 4. row softmax
    softmax_kernel<<<BSZ * NHEADS * SEQ, 256>>>(Ap, attOut, hasAtt);
    // 5. y = A^T V
    {
        dim3 g(SEQ / BM, BSZ * NHEADS);
        av_kernel<<<g, 256>>>(Vp, Ap, attOut, hasAtt, Yp);
    }
    // 6. out projection
    {
        dim3 g(DMODEL / BN, (BSZ * SEQ) / BM);
        outproj_kernel<<<g, 256>>>(Yp, Wout, out);
    }
}

// round 6
// speedup vs baseline: 1.7032x; 1.7032x over previous
#include <cuda_runtime.h>
#include <cuda_bf16.h>
#include <math.h>
#include <stdint.h>

#define BSZ 4
#define SEQ 2048
#define DMODEL 1024
#define NHEADS 8
#define DH 128
#define NEG_INF -1e9f

// ===================== static device scratch =====================
__device__ float g_Q[BSZ * NHEADS * SEQ * DH];
__device__ float g_K[BSZ * NHEADS * SEQ * DH];
__device__ float g_V[BSZ * NHEADS * SEQ * DH];
__device__ float g_AP[SEQ * SEQ];
__device__ float g_A[(size_t)BSZ * NHEADS * SEQ * SEQ];
__device__ float g_Y[BSZ * SEQ * DMODEL];

// ===================== helpers =====================
__device__ __forceinline__ uint32_t smem_u32(const void* p) {
    uint32_t a;
    asm("{ .reg .u64 t; cvta.to.shared.u64 t, %1; cvt.u32.u64 %0, t; }" : "=r"(a) : "l"(p));
    return a;
}
__device__ __forceinline__ void ldsm4(uint32_t* r, uint32_t addr) {
    asm volatile("ldmatrix.sync.aligned.m8n8.x4.shared.b16 {%0,%1,%2,%3}, [%4];"
        : "=r"(r[0]), "=r"(r[1]), "=r"(r[2]), "=r"(r[3]) : "r"(addr));
}
__device__ __forceinline__ void ldsm4_t(uint32_t* r, uint32_t addr) {
    asm volatile("ldmatrix.sync.aligned.m8n8.x4.trans.shared.b16 {%0,%1,%2,%3}, [%4];"
        : "=r"(r[0]), "=r"(r[1]), "=r"(r[2]), "=r"(r[3]) : "r"(addr));
}
__device__ __forceinline__ void mma16816(float* c, const uint32_t* a, uint32_t b0, uint32_t b1) {
    asm volatile("mma.sync.aligned.m16n8k16.row.col.f32.bf16.bf16.f32 "
        "{%0,%1,%2,%3}, {%4,%5,%6,%7}, {%8,%9}, {%0,%1,%2,%3};"
        : "+f"(c[0]), "+f"(c[1]), "+f"(c[2]), "+f"(c[3])
        : "r"(a[0]), "r"(a[1]), "r"(a[2]), "r"(a[3]), "r"(b0), "r"(b1));
}
__device__ __forceinline__ void split4(float4 v, uint2& hi, uint2& lo) {
    __nv_bfloat162 h0 = __floats2bfloat162_rn(v.x, v.y);
    __nv_bfloat162 h1 = __floats2bfloat162_rn(v.z, v.w);
    __nv_bfloat162 l0 = __floats2bfloat162_rn(v.x - __bfloat162float(h0.x),
                                              v.y - __bfloat162float(h0.y));
    __nv_bfloat162 l1 = __floats2bfloat162_rn(v.z - __bfloat162float(h1.x),
                                              v.w - __bfloat162float(h1.y));
    hi.x = *(uint32_t*)&h0; hi.y = *(uint32_t*)&h1;
    lo.x = *(uint32_t*)&l0; lo.y = *(uint32_t*)&l1;
}

// ===================== NT mainloop (A[m][k], B[n][k], fp32 -> bf16x3 mma) ==============
// smem stage: Ahi@0 Alo@10240 Bhi@20480 Blo@30720 ; rows padded to 80B ; 2 stages
#define NT_STAGE 40960
#define NT_SMEM (2 * NT_STAGE)

__device__ __forceinline__ void gemm_nt_mma(
    const float* __restrict__ Ag, int lda,
    const float* __restrict__ Bg, int ldb,
    int K, char* sm, float (&acc)[4][4][4])
{
    const int tid = threadIdx.x, lane = tid & 31, wid = tid >> 5;
    const int morg = (wid >> 2) * 64, norg = (wid & 3) * 32;
    const int lr = tid >> 3, lc = (tid & 7) << 2;
    const uint32_t sbase = smem_u32(sm);
    const int nc = K / 32;
    float4 va[4], vb[4];

    #pragma unroll
    for (int rb = 0; rb < 4; rb++) {
        va[rb] = *(const float4*)(Ag + (size_t)(lr + rb * 32) * lda + lc);
        vb[rb] = *(const float4*)(Bg + (size_t)(lr + rb * 32) * ldb + lc);
    }
    {
        char* st = sm;
        #pragma unroll
        for (int rb = 0; rb < 4; rb++) {
            uint2 hi, lo;
            int off = (lr + rb * 32) * 80 + lc * 2;
            split4(va[rb], hi, lo);
            *(uint2*)(st + off) = hi; *(uint2*)(st + 10240 + off) = lo;
            split4(vb[rb], hi, lo);
            *(uint2*)(st + 20480 + off) = hi; *(uint2*)(st + 30720 + off) = lo;
        }
    }

    for (int c = 0; c < nc; c++) {
        __syncthreads();
        if (c + 1 < nc) {
            #pragma unroll
            for (int rb = 0; rb < 4; rb++) {
                va[rb] = *(const float4*)(Ag + (size_t)(lr + rb * 32) * lda + (c + 1) * 32 + lc);
                vb[rb] = *(const float4*)(Bg + (size_t)(lr + rb * 32) * ldb + (c + 1) * 32 + lc);
            }
        }
        const uint32_t sst = sbase + (c & 1) * NT_STAGE;
        #pragma unroll
        for (int kh = 0; kh < 2; kh++) {
            uint32_t Ah[4][4], Al[4][4], Bh[2][4], Bl[2][4];
            #pragma unroll
            for (int mf = 0; mf < 4; mf++) {
                uint32_t r = morg + mf * 16 + (lane & 15);
                uint32_t ad = sst + r * 80 + ((lane >> 4) << 4) + kh * 32;
                ldsm4(Ah[mf], ad);
                ldsm4(Al[mf], ad + 10240);
            }
            #pragma unroll
            for (int nb = 0; nb < 2; nb++) {
                uint32_t r = norg + nb * 16 + (lane & 7) + ((lane >> 4) << 3);
                uint32_t ad = sst + 20480 + r * 80 + (((lane >> 3) & 1) << 4) + kh * 32;
                ldsm4(Bh[nb], ad);
                ldsm4(Bl[nb], ad + 10240);
            }
            #pragma unroll
            for (int mf = 0; mf < 4; mf++)
                #pragma unroll
                for (int j = 0; j < 4; j++) {
                    uint32_t b0h = Bh[j >> 1][(j & 1) * 2], b1h = Bh[j >> 1][(j & 1) * 2 + 1];
                    uint32_t b0l = Bl[j >> 1][(j & 1) * 2], b1l = Bl[j >> 1][(j & 1) * 2 + 1];
                    mma16816(acc[mf][j], Ah[mf], b0h, b1h);
                    mma16816(acc[mf][j], Ah[mf], b0l, b1l);
                    mma16816(acc[mf][j], Al[mf], b0h, b1h);
                }
        }
        __syncthreads();
        if (c + 1 < nc) {
            char* st = sm + ((c + 1) & 1) * NT_STAGE;
            #pragma unroll
            for (int rb = 0; rb < 4; rb++) {
                uint2 hi, lo;
                int off = (lr + rb * 32) * 80 + lc * 2;
                split4(va[rb], hi, lo);
                *(uint2*)(st + off) = hi; *(uint2*)(st + 10240 + off) = lo;
                split4(vb[rb], hi, lo);
                *(uint2*)(st + 20480 + off) = hi; *(uint2*)(st + 30720 + off) = lo;
            }
        }
    }
}

// ===================== TT mainloop (A stored [k][m], B stored [k][n]) ==============
// smem stage: rows = 32 k, 128 cols bf16, padded to 272B; Ahi@0 Alo@8704 Bhi@17408 Blo@26112
#define TT_STAGE 34816
#define TT_SMEM (2 * TT_STAGE)

__device__ __forceinline__ void gemm_tt_mma(
    const float* __restrict__ Ag, int lda,   // element (k,m): Ag[k*lda + m]
    const float* __restrict__ Bg, int ldb,   // element (k,n)
    int K, char* sm, float (&acc)[4][4][4])
{
    const int tid = threadIdx.x, lane = tid & 31, wid = tid >> 5;
    const int morg = (wid >> 2) * 64, norg = (wid & 3) * 32;
    const int kr = tid >> 5, cg = tid & 31;
    const uint32_t sbase = smem_u32(sm);
    const int nc = K / 32;
    float4 va[4], vb[4];

    #pragma unroll
    for (int rb = 0; rb < 4; rb++) {
        va[rb] = *(const float4*)(Ag + (size_t)(kr + rb * 8) * lda + cg * 4);
        vb[rb] = *(const float4*)(Bg + (size_t)(kr + rb * 8) * ldb + cg * 4);
    }
    {
        char* st = sm;
        #pragma unroll
        for (int rb = 0; rb < 4; rb++) {
            uint2 hi, lo;
            int off = (kr + rb * 8) * 272 + cg * 8;
            split4(va[rb], hi, lo);
            *(uint2*)(st + off) = hi; *(uint2*)(st + 8704 + off) = lo;
            split4(vb[rb], hi, lo);
            *(uint2*)(st + 17408 + off) = hi; *(uint2*)(st + 26112 + off) = lo;
        }
    }

    for (int c = 0; c < nc; c++) {
        __syncthreads();
        if (c + 1 < nc) {
            #pragma unroll
            for (int rb = 0; rb < 4; rb++) {
                va[rb] = *(const float4*)(Ag + (size_t)((c + 1) * 32 + kr + rb * 8) * lda + cg * 4);
                vb[rb] = *(const float4*)(Bg + (size_t)((c + 1) * 32 + kr + rb * 8) * ldb + cg * 4);
            }
        }
        const uint32_t sst = sbase + (c & 1) * TT_STAGE;
        #pragma unroll
        for (int kh = 0; kh < 2; kh++) {
            uint32_t Ah[4][4], Al[4][4], Bh[2][4], Bl[2][4];
            #pragma unroll
            for (int mf = 0; mf < 4; mf++) {
                uint32_t krow = (lane & 7) + ((lane >> 4) << 3) + kh * 16;
                uint32_t ad = sst + krow * 272 + (((lane >> 3) & 1) << 4) + (morg + mf * 16) * 2;
                ldsm4_t(Ah[mf], ad);
                ldsm4_t(Al[mf], ad + 8704);
            }
            #pragma unroll
            for (int nb = 0; nb < 2; nb++) {
                uint32_t krow = (lane & 7) + (((lane >> 3) & 1) << 3) + kh * 16;
                uint32_t ad = sst + 17408 + krow * 272 + ((lane >> 4) << 4) + (norg + nb * 16) * 2;
                ldsm4_t(Bh[nb], ad);
                ldsm4_t(Bl[nb], ad + 8704);
            }
            #pragma unroll
            for (int mf = 0; mf < 4; mf++)
                #pragma unroll
                for (int j = 0; j < 4; j++) {
                    uint32_t b0h = Bh[j >> 1][(j & 1) * 2], b1h = Bh[j >> 1][(j & 1) * 2 + 1];
                    uint32_t b0l = Bl[j >> 1][(j & 1) * 2], b1l = Bl[j >> 1][(j & 1) * 2 + 1];
                    mma16816(acc[mf][j], Ah[mf], b0h, b1h);
                    mma16816(acc[mf][j], Ah[mf], b0l, b1l);
                    mma16816(acc[mf][j], Al[mf], b0h, b1h);
                }
        }
        __syncthreads();
        if (c + 1 < nc) {
            char* st = sm + ((c + 1) & 1) * TT_STAGE;
            #pragma unroll
            for (int rb = 0; rb < 4; rb++) {
                uint2 hi, lo;
                int off = (kr + rb * 8) * 272 + cg * 8;
                split4(va[rb], hi, lo);
                *(uint2*)(st + off) = hi; *(uint2*)(st + 8704 + off) = lo;
                split4(vb[rb], hi, lo);
                *(uint2*)(st + 17408 + off) = hi; *(uint2*)(st + 26112 + off) = lo;
            }
        }
    }
}

// ===================== kernels =====================
__global__ void __launch_bounds__(256) proj_kernel(
    const float* __restrict__ x, const float* __restrict__ W, float* __restrict__ outp)
{
    extern __shared__ char sm[];
    float acc[4][4][4] = {};
    const int tileM = blockIdx.y * 128, tileN = blockIdx.x * 128;
    gemm_nt_mma(x + (size_t)tileM * DMODEL, DMODEL,
                W + (size_t)tileN * DMODEL, DMODEL, DMODEL, sm, acc);

    const int lane = threadIdx.x & 31, wid = threadIdx.x >> 5;
    const int h = blockIdx.x;
    #pragma unroll
    for (int mf = 0; mf < 4; mf++) {
        int row = tileM + (wid >> 2) * 64 + mf * 16 + (lane >> 2);
        #pragma unroll
        for (int j = 0; j < 4; j++) {
            int e = (wid & 3) * 32 + j * 8 + (lane & 3) * 2;
            int b0 = row >> 11, ns0 = row & 2047;
            float* d0 = outp + (((size_t)(b0 * NHEADS + h) * SEQ + ns0) * DH + e);
            *(float2*)d0 = make_float2(acc[mf][j][0], acc[mf][j][1]);
            int r1 = row + 8;
            int b1 = r1 >> 11, ns1 = r1 & 2047;
            float* d1 = outp + (((size_t)(b1 * NHEADS + h) * SEQ + ns1) * DH + e);
            *(float2*)d1 = make_float2(acc[mf][j][2], acc[mf][j][3]);
        }
    }
}

__global__ void __launch_bounds__(256) scores_kernel(
    const float* __restrict__ Q, const float* __restrict__ Km,
    const int* __restrict__ mask, const float* __restrict__ AP,
    float* __restrict__ Abuf, float* __restrict__ attOut, int hasAtt)
{
    extern __shared__ char sm[];
    float acc[4][4][4] = {};
    const int bh = blockIdx.z;
    const int b = bh >> 3, h = bh & 7;
    const size_t hb = (size_t)bh * SEQ * DH;
    const int tileM = blockIdx.y * 128, tileN = blockIdx.x * 128;
    gemm_nt_mma(Q + hb + (size_t)tileM * DH, DH,
                Km + hb + (size_t)tileN * DH, DH, DH, sm, acc);

    float* C = (h == 7 && hasAtt) ? attOut + (size_t)b * SEQ * SEQ
                                  : Abuf   + (size_t)bh * SEQ * SEQ;
    const int lane = threadIdx.x & 31, wid = threadIdx.x >> 5;
    const int* mb = mask + b * SEQ;
    #pragma unroll
    for (int mf = 0; mf < 4; mf++) {
        int r0 = tileM + (wid >> 2) * 64 + mf * 16 + (lane >> 2);
        int r1 = r0 + 8;
        int mr0 = mb[r0], mr1 = mb[r1];
        #pragma unroll
        for (int j = 0; j < 4; j++) {
            int col = tileN + (wid & 3) * 32 + j * 8 + (lane & 3) * 2;
            int mc0 = mb[col], mc1 = mb[col + 1];
            const float* ap0 = AP + (size_t)r0 * SEQ + col;
            const float* ap1 = AP + (size_t)r1 * SEQ + col;
            float2 o0, o1;
            o0.x = (mr0 && mc0) ? acc[mf][j][0] + ap0[0] : NEG_INF;
            o0.y = (mr0 && mc1) ? acc[mf][j][1] + ap0[1] : NEG_INF;
            o1.x = (mr1 && mc0) ? acc[mf][j][2] + ap1[0] : NEG_INF;
            o1.y = (mr1 && mc1) ? acc[mf][j][3] + ap1[1] : NEG_INF;
            *(float2*)(C + (size_t)r0 * SEQ + col) = o0;
            *(float2*)(C + (size_t)r1 * SEQ + col) = o1;
        }
    }
}

__global__ void __launch_bounds__(256) av_kernel(
    const float* __restrict__ V, const float* __restrict__ Abuf,
    const float* __restrict__ attOut, int hasAtt, float* __restrict__ Y)
{
    extern __shared__ char sm[];
    float acc[4][4][4] = {};
    const int bh = blockIdx.y;
    const int b = bh >> 3, h = bh & 7;
    const float* Abase = (h == 7 && hasAtt) ? attOut + (size_t)b * SEQ * SEQ
                                            : Abuf   + (size_t)bh * SEQ * SEQ;
    const float* Vb = V + (size_t)bh * SEQ * DH;
    const int tileM = blockIdx.x * 128;
    gemm_tt_mma(Abase + tileM, SEQ, Vb, DH, SEQ, sm, acc);

    const int lane = threadIdx.x & 31, wid = threadIdx.x >> 5;
    #pragma unroll
    for (int mf = 0; mf < 4; mf++) {
        int i0 = tileM + (wid >> 2) * 64 + mf * 16 + (lane >> 2);
        #pragma unroll
        for (int j = 0; j < 4; j++) {
            int e = (wid & 3) * 32 + j * 8 + (lane & 3) * 2;
            float* d0 = Y + ((size_t)b * SEQ + i0) * DMODEL + h * DH + e;
            float* d1 = Y + ((size_t)b * SEQ + i0 + 8) * DMODEL + h * DH + e;
            *(float2*)d0 = make_float2(acc[mf][j][0], acc[mf][j][1]);
            *(float2*)d1 = make_float2(acc[mf][j][2], acc[mf][j][3]);
        }
    }
}

__global__ void __launch_bounds__(256) outproj_kernel(
    const float* __restrict__ Y, const float* __restrict__ Wout, float* __restrict__ out)
{
    extern __shared__ char sm[];
    float acc[4][4][4] = {};
    const int tileM = blockIdx.y * 128, tileN = blockIdx.x * 128;
    gemm_nt_mma(Y + (size_t)tileM * DMODEL, DMODEL,
                Wout + (size_t)tileN * DMODEL, DMODEL, DMODEL, sm, acc);

    const int lane = threadIdx.x & 31, wid = threadIdx.x >> 5;
    #pragma unroll
    for (int mf = 0; mf < 4; mf++) {
        int row = tileM + (wid >> 2) * 64 + mf * 16 + (lane >> 2);
        #pragma unroll
        for (int j = 0; j < 4; j++) {
            int col = tileN + (wid & 3) * 32 + j * 8 + (lane & 3) * 2;
            *(float2*)(out + (size_t)row * DMODEL + col) =
                make_float2(acc[mf][j][0], acc[mf][j][1]);
            *(float2*)(out + (size_t)(row + 8) * DMODEL + col) =
                make_float2(acc[mf][j][2], acc[mf][j][3]);
        }
    }
}

// ===================== AP + softmax =====================
__global__ void ap_kernel(float* __restrict__ AP) {
    int idx = blockIdx.x * blockDim.x + threadIdx.x;
    const int total = SEQ * (SEQ / 2);
    if (idx >= total) return;
    int p = idx / (SEQ / 2);
    int i = idx % (SEQ / 2);
    float denom = powf(10000.0f, (2.0f * (float)i) / 1024.0f);
    float angle = (float)p / denom;
    float s, c;
    sincosf(angle, &s, &c);
    AP[(size_t)p * SEQ + 2 * i]     = s;
    AP[(size_t)p * SEQ + 2 * i + 1] = c;
}

__global__ void __launch_bounds__(256) softmax_kernel(
    float* __restrict__ Abuf, float* __restrict__ attOut, int hasAtt)
{
    const int row = blockIdx.x;
    const int bh = row >> 11;
    const int q  = row & 2047;
    const int b = bh >> 3, h = bh & 7;
    float* base = (h == 7 && hasAtt) ? attOut + (size_t)b * SEQ * SEQ
                                     : Abuf   + (size_t)bh * SEQ * SEQ;
    float* rp = base + (size_t)q * SEQ;

    const int t = threadIdx.x;
    float v[8];
    #pragma unroll
    for (int i = 0; i < 8; i++) v[i] = rp[t + i * 256];
    float m = v[0];
    #pragma unroll
    for (int i = 1; i < 8; i++) m = fmaxf(m, v[i]);

    __shared__ float sdata[256];
    sdata[t] = m;
    __syncthreads();
    for (int s = 128; s > 0; s >>= 1) {
        if (t < s) sdata[t] = fmaxf(sdata[t], sdata[t + s]);
        __syncthreads();
    }
    const float mx = sdata[0];
    __syncthreads();
    float sum = 0.f;
    #pragma unroll
    for (int i = 0; i < 8; i++) { v[i] = expf(v[i] - mx); sum += v[i]; }
    sdata[t] = sum;
    __syncthreads();
    for (int s = 128; s > 0; s >>= 1) {
        if (t < s) sdata[t] += sdata[t + s];
        __syncthreads();
    }
    const float inv = 1.0f / sdata[0];
    #pragma unroll
    for (int i = 0; i < 8; i++) rp[t + i * 256] = v[i] * inv;
}

// ===================== launch =====================
extern "C" void kernel_launch(void* const* d_in, const int* in_sizes, int n_in,
                              void* d_out, int out_size) {
    const float* x    = (const float*)d_in[0];
    const int*   mask = (const int*)  d_in[1];
    const float* Wq   = (const float*)d_in[2];
    const float* Wk   = (const float*)d_in[3];
    const float* Wv   = (const float*)d_in[4];
    const float* Wout = (const float*)d_in[5];
    float* out = (float*)d_out;

    const long long outElems = (long long)BSZ * SEQ * DMODEL;
    const long long attElems = (long long)BSZ * SEQ * SEQ;
    int hasAtt = ((long long)out_size >= outElems + attElems) ? 1 : 0;
    float* attOut = out + outElems;

    float *Qp, *Kp, *Vp, *APp, *Ap, *Yp;
    cudaGetSymbolAddress((void**)&Qp,  g_Q);
    cudaGetSymbolAddress((void**)&Kp,  g_K);
    cudaGetSymbolAddress((void**)&Vp,  g_V);
    cudaGetSymbolAddress((void**)&APp, g_AP);
    cudaGetSymbolAddress((void**)&Ap,  g_A);
    cudaGetSymbolAddress((void**)&Yp,  g_Y);

    cudaFuncSetAttribute(proj_kernel,    cudaFuncAttributeMaxDynamicSharedMemorySize, NT_SMEM);
    cudaFuncSetAttribute(scores_kernel,  cudaFuncAttributeMaxDynamicSharedMemorySize, NT_SMEM);
    cudaFuncSetAttribute(outproj_kernel, cudaFuncAttributeMaxDynamicSharedMemorySize, NT_SMEM);
    cudaFuncSetAttribute(av_kernel,      cudaFuncAttributeMaxDynamicSharedMemorySize, TT_SMEM);

    // 1. AP table
    {
        int total = SEQ * (SEQ / 2);
        ap_kernel<<<(total + 255) / 256, 256>>>(APp);
    }
    // 2. projections (mma.sync bf16x3)
    {
        dim3 g(DMODEL / 128, (BSZ * SEQ) / 128);
        proj_kernel<<<g, 256, NT_SMEM>>>(x, Wq, Qp);
        proj_kernel<<<g, 256, NT_SMEM>>>(x, Wk, Kp);
        proj_kernel<<<g, 256, NT_SMEM>>>(x, Wv, Vp);
    }
    // 3. scores
    {
        dim3 g(SEQ / 128, SEQ / 128, BSZ * NHEADS);
        scores_kernel<<<g, 256, NT_SMEM>>>(Qp, Kp, mask, APp, Ap, attOut, hasAtt);
    }
    // 4. softmax
    softmax_kernel<<<BSZ * NHEADS * SEQ, 256>>>(Ap, attOut, hasAtt);
    // 5. y = A^T V
    {
        dim3 g(SEQ / 128, BSZ * NHEADS);
        av_kernel<<<g, 256, TT_SMEM>>>(Vp, Ap, attOut, hasAtt, Yp);
    }
    // 6. out projection
    {
        dim3 g(DMODEL / 128, (BSZ * SEQ) / 128);
        outproj_kernel<<<g, 256, NT_SMEM>>>(Yp, Wout, out);
    }
}

// round 7
// speedup vs baseline: 2.1087x; 1.2381x over previous
#include <cuda_runtime.h>
#include <cuda_bf16.h>
#include <math.h>
#include <stdint.h>

#define BSZ 4
#define SEQ 2048
#define DMODEL 1024
#define NHEADS 8
#define DH 128
#define NEG_INF -1e9f

// ===================== static device scratch =====================
__device__ float g_Q[BSZ * NHEADS * SEQ * DH];
__device__ float g_K[BSZ * NHEADS * SEQ * DH];
__device__ float g_V[BSZ * NHEADS * SEQ * DH];
__device__ float g_AP[SEQ * SEQ];
__device__ float g_A[(size_t)BSZ * NHEADS * SEQ * SEQ];
__device__ float g_Y[BSZ * SEQ * DMODEL];

// ===================== helpers =====================
__device__ __forceinline__ uint32_t smem_u32(const void* p) {
    uint32_t a;
    asm("{ .reg .u64 t; cvta.to.shared.u64 t, %1; cvt.u32.u64 %0, t; }" : "=r"(a) : "l"(p));
    return a;
}
__device__ __forceinline__ void ldsm4(uint32_t* r, uint32_t addr) {
    asm volatile("ldmatrix.sync.aligned.m8n8.x4.shared.b16 {%0,%1,%2,%3}, [%4];"
        : "=r"(r[0]), "=r"(r[1]), "=r"(r[2]), "=r"(r[3]) : "r"(addr));
}
__device__ __forceinline__ void ldsm4_t(uint32_t* r, uint32_t addr) {
    asm volatile("ldmatrix.sync.aligned.m8n8.x4.trans.shared.b16 {%0,%1,%2,%3}, [%4];"
        : "=r"(r[0]), "=r"(r[1]), "=r"(r[2]), "=r"(r[3]) : "r"(addr));
}
__device__ __forceinline__ void mma16816(float* c, const uint32_t* a, uint32_t b0, uint32_t b1) {
    asm volatile("mma.sync.aligned.m16n8k16.row.col.f32.bf16.bf16.f32 "
        "{%0,%1,%2,%3}, {%4,%5,%6,%7}, {%8,%9}, {%0,%1,%2,%3};"
        : "+f"(c[0]), "+f"(c[1]), "+f"(c[2]), "+f"(c[3])
        : "r"(a[0]), "r"(a[1]), "r"(a[2]), "r"(a[3]), "r"(b0), "r"(b1));
}
__device__ __forceinline__ void split4(float4 v, uint2& hi, uint2& lo) {
    __nv_bfloat162 h0 = __floats2bfloat162_rn(v.x, v.y);
    __nv_bfloat162 h1 = __floats2bfloat162_rn(v.z, v.w);
    __nv_bfloat162 l0 = __floats2bfloat162_rn(v.x - __bfloat162float(h0.x),
                                              v.y - __bfloat162float(h0.y));
    __nv_bfloat162 l1 = __floats2bfloat162_rn(v.z - __bfloat162float(h1.x),
                                              v.w - __bfloat162float(h1.y));
    hi.x = *(uint32_t*)&h0; hi.y = *(uint32_t*)&h1;
    lo.x = *(uint32_t*)&l0; lo.y = *(uint32_t*)&l1;
}

// ===================== NT mainloop (A[m][k], B[n][k], fp32 -> bf16x3 mma) ==============
// smem stage: Ahi@0 Alo@10240 Bhi@20480 Blo@30720 ; rows padded to 80B ; 2 stages
#define NT_STAGE 40960
#define NT_SMEM (2 * NT_STAGE)

__device__ __forceinline__ void gemm_nt_mma(
    const float* __restrict__ Ag, int lda,
    const float* __restrict__ Bg, int ldb,
    int K, char* sm, float (&acc)[4][4][4])
{
    const int tid = threadIdx.x, lane = tid & 31, wid = tid >> 5;
    const int morg = (wid >> 2) * 64, norg = (wid & 3) * 32;
    const int lr = tid >> 3, lc = (tid & 7) << 2;
    const uint32_t sbase = smem_u32(sm);
    const int nc = K / 32;
    float4 va[4], vb[4];

    #pragma unroll
    for (int rb = 0; rb < 4; rb++) {
        va[rb] = *(const float4*)(Ag + (size_t)(lr + rb * 32) * lda + lc);
        vb[rb] = *(const float4*)(Bg + (size_t)(lr + rb * 32) * ldb + lc);
    }
    {
        char* st = sm;
        #pragma unroll
        for (int rb = 0; rb < 4; rb++) {
            uint2 hi, lo;
            int off = (lr + rb * 32) * 80 + lc * 2;
            split4(va[rb], hi, lo);
            *(uint2*)(st + off) = hi; *(uint2*)(st + 10240 + off) = lo;
            split4(vb[rb], hi, lo);
            *(uint2*)(st + 20480 + off) = hi; *(uint2*)(st + 30720 + off) = lo;
        }
    }

    for (int c = 0; c < nc; c++) {
        __syncthreads();
        if (c + 1 < nc) {
            #pragma unroll
            for (int rb = 0; rb < 4; rb++) {
                va[rb] = *(const float4*)(Ag + (size_t)(lr + rb * 32) * lda + (c + 1) * 32 + lc);
                vb[rb] = *(const float4*)(Bg + (size_t)(lr + rb * 32) * ldb + (c + 1) * 32 + lc);
            }
        }
        const uint32_t sst = sbase + (c & 1) * NT_STAGE;
        #pragma unroll
        for (int kh = 0; kh < 2; kh++) {
            uint32_t Ah[4][4], Al[4][4], Bh[2][4], Bl[2][4];
            #pragma unroll
            for (int mf = 0; mf < 4; mf++) {
                uint32_t r = morg + mf * 16 + (lane & 15);
                uint32_t ad = sst + r * 80 + ((lane >> 4) << 4) + kh * 32;
                ldsm4(Ah[mf], ad);
                ldsm4(Al[mf], ad + 10240);
            }
            #pragma unroll
            for (int nb = 0; nb < 2; nb++) {
                uint32_t r = norg + nb * 16 + (lane & 7) + ((lane >> 4) << 3);
                uint32_t ad = sst + 20480 + r * 80 + (((lane >> 3) & 1) << 4) + kh * 32;
                ldsm4(Bh[nb], ad);
                ldsm4(Bl[nb], ad + 10240);
            }
            #pragma unroll
            for (int mf = 0; mf < 4; mf++)
                #pragma unroll
                for (int j = 0; j < 4; j++) {
                    uint32_t b0h = Bh[j >> 1][(j & 1) * 2], b1h = Bh[j >> 1][(j & 1) * 2 + 1];
                    uint32_t b0l = Bl[j >> 1][(j & 1) * 2], b1l = Bl[j >> 1][(j & 1) * 2 + 1];
                    mma16816(acc[mf][j], Ah[mf], b0h, b1h);
                    mma16816(acc[mf][j], Ah[mf], b0l, b1l);
                    mma16816(acc[mf][j], Al[mf], b0h, b1h);
                }
        }
        __syncthreads();
        if (c + 1 < nc) {
            char* st = sm + ((c + 1) & 1) * NT_STAGE;
            #pragma unroll
            for (int rb = 0; rb < 4; rb++) {
                uint2 hi, lo;
                int off = (lr + rb * 32) * 80 + lc * 2;
                split4(va[rb], hi, lo);
                *(uint2*)(st + off) = hi; *(uint2*)(st + 10240 + off) = lo;
                split4(vb[rb], hi, lo);
                *(uint2*)(st + 20480 + off) = hi; *(uint2*)(st + 30720 + off) = lo;
            }
        }
    }
}

// ===================== TT mainloop (A stored [k][m], B stored [k][n]) ==============
// smem stage: rows = 32 k, 128 cols bf16, padded to 272B; Ahi@0 Alo@8704 Bhi@17408 Blo@26112
#define TT_STAGE 34816
#define TT_SMEM (2 * TT_STAGE)

__device__ __forceinline__ void gemm_tt_mma(
    const float* __restrict__ Ag, int lda,   // element (k,m): Ag[k*lda + m]
    const float* __restrict__ Bg, int ldb,   // element (k,n)
    int K, char* sm, float (&acc)[4][4][4])
{
    const int tid = threadIdx.x, lane = tid & 31, wid = tid >> 5;
    const int morg = (wid >> 2) * 64, norg = (wid & 3) * 32;
    const int kr = tid >> 5, cg = tid & 31;
    const uint32_t sbase = smem_u32(sm);
    const int nc = K / 32;
    float4 va[4], vb[4];

    #pragma unroll
    for (int rb = 0; rb < 4; rb++) {
        va[rb] = *(const float4*)(Ag + (size_t)(kr + rb * 8) * lda + cg * 4);
        vb[rb] = *(const float4*)(Bg + (size_t)(kr + rb * 8) * ldb + cg * 4);
    }
    {
        char* st = sm;
        #pragma unroll
        for (int rb = 0; rb < 4; rb++) {
            uint2 hi, lo;
            int off = (kr + rb * 8) * 272 + cg * 8;
            split4(va[rb], hi, lo);
            *(uint2*)(st + off) = hi; *(uint2*)(st + 8704 + off) = lo;
            split4(vb[rb], hi, lo);
            *(uint2*)(st + 17408 + off) = hi; *(uint2*)(st + 26112 + off) = lo;
        }
    }

    for (int c = 0; c < nc; c++) {
        __syncthreads();
        if (c + 1 < nc) {
            #pragma unroll
            for (int rb = 0; rb < 4; rb++) {
                va[rb] = *(const float4*)(Ag + (size_t)((c + 1) * 32 + kr + rb * 8) * lda + cg * 4);
                vb[rb] = *(const float4*)(Bg + (size_t)((c + 1) * 32 + kr + rb * 8) * ldb + cg * 4);
            }
        }
        const uint32_t sst = sbase + (c & 1) * TT_STAGE;
        #pragma unroll
        for (int kh = 0; kh < 2; kh++) {
            uint32_t Ah[4][4], Al[4][4], Bh[2][4], Bl[2][4];
            #pragma unroll
            for (int mf = 0; mf < 4; mf++) {
                uint32_t krow = (lane & 7) + ((lane >> 4) << 3) + kh * 16;
                uint32_t ad = sst + krow * 272 + (((lane >> 3) & 1) << 4) + (morg + mf * 16) * 2;
                ldsm4_t(Ah[mf], ad);
                ldsm4_t(Al[mf], ad + 8704);
            }
            #pragma unroll
            for (int nb = 0; nb < 2; nb++) {
                uint32_t krow = (lane & 7) + (((lane >> 3) & 1) << 3) + kh * 16;
                uint32_t ad = sst + 17408 + krow * 272 + ((lane >> 4) << 4) + (norg + nb * 16) * 2;
                ldsm4_t(Bh[nb], ad);
                ldsm4_t(Bl[nb], ad + 8704);
            }
            #pragma unroll
            for (int mf = 0; mf < 4; mf++)
                #pragma unroll
                for (int j = 0; j < 4; j++) {
                    uint32_t b0h = Bh[j >> 1][(j & 1) * 2], b1h = Bh[j >> 1][(j & 1) * 2 + 1];
                    uint32_t b0l = Bl[j >> 1][(j & 1) * 2], b1l = Bl[j >> 1][(j & 1) * 2 + 1];
                    mma16816(acc[mf][j], Ah[mf], b0h, b1h);
                    mma16816(acc[mf][j], Ah[mf], b0l, b1l);
                    mma16816(acc[mf][j], Al[mf], b0h, b1h);
                }
        }
        __syncthreads();
        if (c + 1 < nc) {
            char* st = sm + ((c + 1) & 1) * TT_STAGE;
            #pragma unroll
            for (int rb = 0; rb < 4; rb++) {
                uint2 hi, lo;
                int off = (kr + rb * 8) * 272 + cg * 8;
                split4(va[rb], hi, lo);
                *(uint2*)(st + off) = hi; *(uint2*)(st + 8704 + off) = lo;
                split4(vb[rb], hi, lo);
                *(uint2*)(st + 17408 + off) = hi; *(uint2*)(st + 26112 + off) = lo;
            }
        }
    }
}

// ===================== kernels =====================
__global__ void __launch_bounds__(256, 2) proj_kernel(
    const float* __restrict__ x, const float* __restrict__ W, float* __restrict__ outp)
{
    extern __shared__ char sm[];
    float acc[4][4][4] = {};
    const int tileM = blockIdx.y * 128, tileN = blockIdx.x * 128;
    gemm_nt_mma(x + (size_t)tileM * DMODEL, DMODEL,
                W + (size_t)tileN * DMODEL, DMODEL, DMODEL, sm, acc);

    const int lane = threadIdx.x & 31, wid = threadIdx.x >> 5;
    const int h = blockIdx.x;
    #pragma unroll
    for (int mf = 0; mf < 4; mf++) {
        int row = tileM + (wid >> 2) * 64 + mf * 16 + (lane >> 2);
        #pragma unroll
        for (int j = 0; j < 4; j++) {
            int e = (wid & 3) * 32 + j * 8 + (lane & 3) * 2;
            int b0 = row >> 11, ns0 = row & 2047;
            float* d0 = outp + (((size_t)(b0 * NHEADS + h) * SEQ + ns0) * DH + e);
            *(float2*)d0 = make_float2(acc[mf][j][0], acc[mf][j][1]);
            int r1 = row + 8;
            int b1 = r1 >> 11, ns1 = r1 & 2047;
            float* d1 = outp + (((size_t)(b1 * NHEADS + h) * SEQ + ns1) * DH + e);
            *(float2*)d1 = make_float2(acc[mf][j][2], acc[mf][j][3]);
        }
    }
}

__global__ void __launch_bounds__(256, 2) scores_kernel(
    const float* __restrict__ Q, const float* __restrict__ Km,
    const int* __restrict__ mask, const float* __restrict__ AP,
    float* __restrict__ Abuf, float* __restrict__ attOut, int hasAtt)
{
    extern __shared__ char sm[];
    float acc[4][4][4] = {};
    const int bh = blockIdx.z;
    const int b = bh >> 3, h = bh & 7;
    const size_t hb = (size_t)bh * SEQ * DH;
    const int tileM = blockIdx.y * 128, tileN = blockIdx.x * 128;
    gemm_nt_mma(Q + hb + (size_t)tileM * DH, DH,
                Km + hb + (size_t)tileN * DH, DH, DH, sm, acc);

    float* C = (h == 7 && hasAtt) ? attOut + (size_t)b * SEQ * SEQ
                                  : Abuf   + (size_t)bh * SEQ * SEQ;
    const int lane = threadIdx.x & 31, wid = threadIdx.x >> 5;
    const int* mb = mask + b * SEQ;
    #pragma unroll
    for (int mf = 0; mf < 4; mf++) {
        int r0 = tileM + (wid >> 2) * 64 + mf * 16 + (lane >> 2);
        int r1 = r0 + 8;
        int mr0 = mb[r0], mr1 = mb[r1];
        #pragma unroll
        for (int j = 0; j < 4; j++) {
            int col = tileN + (wid & 3) * 32 + j * 8 + (lane & 3) * 2;
            int mc0 = mb[col], mc1 = mb[col + 1];
            const float* ap0 = AP + (size_t)r0 * SEQ + col;
            const float* ap1 = AP + (size_t)r1 * SEQ + col;
            float2 o0, o1;
            o0.x = (mr0 && mc0) ? acc[mf][j][0] + ap0[0] : NEG_INF;
            o0.y = (mr0 && mc1) ? acc[mf][j][1] + ap0[1] : NEG_INF;
            o1.x = (mr1 && mc0) ? acc[mf][j][2] + ap1[0] : NEG_INF;
            o1.y = (mr1 && mc1) ? acc[mf][j][3] + ap1[1] : NEG_INF;
            *(float2*)(C + (size_t)r0 * SEQ + col) = o0;
            *(float2*)(C + (size_t)r1 * SEQ + col) = o1;
        }
    }
}

__global__ void __launch_bounds__(256, 2) av_kernel(
    const float* __restrict__ V, const float* __restrict__ Abuf,
    const float* __restrict__ attOut, int hasAtt, float* __restrict__ Y)
{
    extern __shared__ char sm[];
    float acc[4][4][4] = {};
    const int bh = blockIdx.y;
    const int b = bh >> 3, h = bh & 7;
    const float* Abase = (h == 7 && hasAtt) ? attOut + (size_t)b * SEQ * SEQ
                                            : Abuf   + (size_t)bh * SEQ * SEQ;
    const float* Vb = V + (size_t)bh * SEQ * DH;
    const int tileM = blockIdx.x * 128;
    gemm_tt_mma(Abase + tileM, SEQ, Vb, DH, SEQ, sm, acc);

    const int lane = threadIdx.x & 31, wid = threadIdx.x >> 5;
    #pragma unroll
    for (int mf = 0; mf < 4; mf++) {
        int i0 = tileM + (wid >> 2) * 64 + mf * 16 + (lane >> 2);
        #pragma unroll
        for (int j = 0; j < 4; j++) {
            int e = (wid & 3) * 32 + j * 8 + (lane & 3) * 2;
            float* d0 = Y + ((size_t)b * SEQ + i0) * DMODEL + h * DH + e;
            float* d1 = Y + ((size_t)b * SEQ + i0 + 8) * DMODEL + h * DH + e;
            *(float2*)d0 = make_float2(acc[mf][j][0], acc[mf][j][1]);
            *(float2*)d1 = make_float2(acc[mf][j][2], acc[mf][j][3]);
        }
    }
}

__global__ void __launch_bounds__(256, 2) outproj_kernel(
    const float* __restrict__ Y, const float* __restrict__ Wout, float* __restrict__ out)
{
    extern __shared__ char sm[];
    float acc[4][4][4] = {};
    const int tileM = blockIdx.y * 128, tileN = blockIdx.x * 128;
    gemm_nt_mma(Y + (size_t)tileM * DMODEL, DMODEL,
                Wout + (size_t)tileN * DMODEL, DMODEL, DMODEL, sm, acc);

    const int lane = threadIdx.x & 31, wid = threadIdx.x >> 5;
    #pragma unroll
    for (int mf = 0; mf < 4; mf++) {
        int row = tileM + (wid >> 2) * 64 + mf * 16 + (lane >> 2);
        #pragma unroll
        for (int j = 0; j < 4; j++) {
            int col = tileN + (wid & 3) * 32 + j * 8 + (lane & 3) * 2;
            *(float2*)(out + (size_t)row * DMODEL + col) =
                make_float2(acc[mf][j][0], acc[mf][j][1]);
            *(float2*)(out + (size_t)(row + 8) * DMODEL + col) =
                make_float2(acc[mf][j][2], acc[mf][j][3]);
        }
    }
}

// ===================== AP + softmax =====================
__global__ void ap_kernel(float* __restrict__ AP) {
    int idx = blockIdx.x * blockDim.x + threadIdx.x;
    const int total = SEQ * (SEQ / 2);
    if (idx >= total) return;
    int p = idx / (SEQ / 2);
    int i = idx % (SEQ / 2);
    float denom = powf(10000.0f, (2.0f * (float)i) / 1024.0f);
    float angle = (float)p / denom;
    float s, c;
    sincosf(angle, &s, &c);
    AP[(size_t)p * SEQ + 2 * i]     = s;
    AP[(size_t)p * SEQ + 2 * i + 1] = c;
}

__global__ void __launch_bounds__(256) softmax_kernel(
    float* __restrict__ Abuf, float* __restrict__ attOut, int hasAtt)
{
    const int row = blockIdx.x;
    const int bh = row >> 11;
    const int q  = row & 2047;
    const int b = bh >> 3, h = bh & 7;
    float* base = (h == 7 && hasAtt) ? attOut + (size_t)b * SEQ * SEQ
                                     : Abuf   + (size_t)bh * SEQ * SEQ;
    float4* rp = (float4*)(base + (size_t)q * SEQ);

    const int t = threadIdx.x;
    float4 u = rp[2 * t], w = rp[2 * t + 1];

    float m = fmaxf(fmaxf(fmaxf(u.x, u.y), fmaxf(u.z, u.w)),
                    fmaxf(fmaxf(w.x, w.y), fmaxf(w.z, w.w)));
    __shared__ float sdata[256];
    sdata[t] = m;
    __syncthreads();
    for (int s = 128; s > 0; s >>= 1) {
        if (t < s) sdata[t] = fmaxf(sdata[t], sdata[t + s]);
        __syncthreads();
    }
    const float mx = sdata[0];
    __syncthreads();

    u.x = expf(u.x - mx); u.y = expf(u.y - mx); u.z = expf(u.z - mx); u.w = expf(u.w - mx);
    w.x = expf(w.x - mx); w.y = expf(w.y - mx); w.z = expf(w.z - mx); w.w = expf(w.w - mx);
    float sum = (u.x + u.y) + (u.z + u.w) + (w.x + w.y) + (w.z + w.w);
    sdata[t] = sum;
    __syncthreads();
    for (int s = 128; s > 0; s >>= 1) {
        if (t < s) sdata[t] += sdata[t + s];
        __syncthreads();
    }
    const float inv = 1.0f / sdata[0];
    u.x *= inv; u.y *= inv; u.z *= inv; u.w *= inv;
    w.x *= inv; w.y *= inv; w.z *= inv; w.w *= inv;
    rp[2 * t] = u;
    rp[2 * t + 1] = w;
}

// ===================== launch =====================
extern "C" void kernel_launch(void* const* d_in, const int* in_sizes, int n_in,
                              void* d_out, int out_size) {
    const float* x    = (const float*)d_in[0];
    const int*   mask = (const int*)  d_in[1];
    const float* Wq   = (const float*)d_in[2];
    const float* Wk   = (const float*)d_in[3];
    const float* Wv   = (const float*)d_in[4];
    const float* Wout = (const float*)d_in[5];
    float* out = (float*)d_out;

    const long long outElems = (long long)BSZ * SEQ * DMODEL;
    const long long attElems = (long long)BSZ * SEQ * SEQ;
    int hasAtt = ((long long)out_size >= outElems + attElems) ? 1 : 0;
    float* attOut = out + outElems;

    float *Qp, *Kp, *Vp, *APp, *Ap, *Yp;
    cudaGetSymbolAddress((void**)&Qp,  g_Q);
    cudaGetSymbolAddress((void**)&Kp,  g_K);
    cudaGetSymbolAddress((void**)&Vp,  g_V);
    cudaGetSymbolAddress((void**)&APp, g_AP);
    cudaGetSymbolAddress((void**)&Ap,  g_A);
    cudaGetSymbolAddress((void**)&Yp,  g_Y);

    cudaFuncSetAttribute(proj_kernel,    cudaFuncAttributeMaxDynamicSharedMemorySize, NT_SMEM);
    cudaFuncSetAttribute(scores_kernel,  cudaFuncAttributeMaxDynamicSharedMemorySize, NT_SMEM);
    cudaFuncSetAttribute(outproj_kernel, cudaFuncAttributeMaxDynamicSharedMemorySize, NT_SMEM);
    cudaFuncSetAttribute(av_kernel,      cudaFuncAttributeMaxDynamicSharedMemorySize, TT_SMEM);

    // 1. AP table
    {
        int total = SEQ * (SEQ / 2);
        ap_kernel<<<(total + 255) / 256, 256>>>(APp);
    }
    // 2. projections (mma.sync bf16x3)
    {
        dim3 g(DMODEL / 128, (BSZ * SEQ) / 128);
        proj_kernel<<<g, 256, NT_SMEM>>>(x, Wq, Qp);
        proj_kernel<<<g, 256, NT_SMEM>>>(x, Wk, Kp);
        proj_kernel<<<g, 256, NT_SMEM>>>(x, Wv, Vp);
    }
    // 3. scores
    {
        dim3 g(SEQ / 128, SEQ / 128, BSZ * NHEADS);
        scores_kernel<<<g, 256, NT_SMEM>>>(Qp, Kp, mask, APp, Ap, attOut, hasAtt);
    }
    // 4. softmax
    softmax_kernel<<<BSZ * NHEADS * SEQ, 256>>>(Ap, attOut, hasAtt);
    // 5. y = A^T V
    {
        dim3 g(SEQ / 128, BSZ * NHEADS);
        av_kernel<<<g, 256, TT_SMEM>>>(Vp, Ap, attOut, hasAtt, Yp);
    }
    // 6. out projection
    {
        dim3 g(DMODEL / 128, (BSZ * SEQ) / 128);
        outproj_kernel<<<g, 256, NT_SMEM>>>(Yp, Wout, out);
    }
}